// round 13
// baseline (speedup 1.0000x reference)
#include <cuda_runtime.h>
#include <cstdint>

// EPG simulation, 8 threads per batch: threads 0-6 own 3 EPG states each
// (21 = 7*3); thread 7 is pinned to zero and supplies the Fm[20]=0 boundary.
// R13: sweep-first restructure -- the slot-2 carry produced by the sweep IS
// the boundary-out value (previously computed twice); shuffle after the sweep
// and patch slot 0 / slot 2. Double-buffer pointers hoisted.

constexpr int NS   = 21;
constexpr int ROW  = NS * 5;            // 105 floats per (pulse,batch)
constexpr int NP   = 64;
constexpr int WARPS = 4;                // warps per block
constexpr int THREADS = WARPS * 32;     // 128 threads -> 16 batches per block
constexpr int BPW  = 4;                 // batches per warp (8 threads each)
constexpr int WST  = BPW * ROW;         // 420 floats per warp stage
constexpr int WST4 = WST / 4;           // 105 float4

__global__ __launch_bounds__(THREADS)
void epg_kernel(const float* __restrict__ fa,
                const float* __restrict__ ph,
                const float* __restrict__ T1,
                const float* __restrict__ T2,
                const float* __restrict__ B0,
                const float* __restrict__ B1,
                const int*   __restrict__ trp,
                float* __restrict__ out,
                int n_pulses, int n_batch)
{
    __shared__ __align__(16) float4 pc4[NP];              // {fa, cos p, sin p, cos 2p}
    __shared__ float                ps2[NP];              // sin 2p
    __shared__ __align__(16) float  stage[WARPS][2][WST]; // double-buffered

    const int tid  = threadIdx.x;
    const int warp = tid >> 5;
    const int lane = tid & 31;
    const int bw   = lane >> 3;          // batch within warp (0..3)
    const int t    = lane & 7;           // fragment within batch (0..7)

    for (int p = tid; p < n_pulses; p += THREADS) {
        float s, c;
        sincosf(ph[p], &s, &c);
        pc4[p] = make_float4(fa[p], c, s, c * c - s * s);
        ps2[p] = 2.f * c * s;
    }
    __syncthreads();

    int b = blockIdx.x * (WARPS * BPW) + warp * BPW + bw;
    if (b >= n_batch) b = n_batch - 1;   // 16384 % 16 == 0: never taken

    const int tri = *trp;
    const float TR = (tri > 0 && tri < 1000000) ? (float)tri : __int_as_float(tri);

    const float E1  = __expf(-TR / T1[b]);
    const float E2  = __expf(-TR / T2[b]);
    const float rec = 1.f - E1;
    const float b1h = B1[b] * 0.5f;
    float b0r, b0i;
    sincosf(6.283185307179586e-3f * B0[b] * TR, &b0i, &b0r);
    const float er = E2 * b0r, ei = E2 * b0i;   // E2 * e^{i theta}

    // 3 local slots; global state k = 3*t + j for t<=6; t==7 stays zero.
    float Fpr[3], Fpi[3], Fmr[3], Fmi[3], Zz[3];
    #pragma unroll
    for (int j = 0; j < 3; ++j) { Fpr[j]=0.f; Fpi[j]=0.f; Fmr[j]=0.f; Fmi[j]=0.f; Zz[j]=0.f; }
    const bool t0 = (t == 0), t7 = (t == 7);
    if (t0) Zz[0] = 1.f;

    const size_t pst4 = (size_t)n_batch * ROW / 4;
    float4* out4 = (float4*)out
                 + ((size_t)blockIdx.x * (WARPS * BPW) + warp * BPW) * ROW / 4;

    // Hoisted double-buffer pointers
    float* const row0 = &stage[warp][0][bw * ROW + t * 15];
    float* const row1 = &stage[warp][1][bw * ROW + t * 15];
    const float4* const s40 = (const float4*)stage[warp][0];
    const float4* const s41 = (const float4*)stage[warp][1];

    for (int p = 0; p < n_pulses; ++p) {
        const float4 pc = pc4[p];
        const float  s2 = ps2[p];
        const float  cp = pc.y, sp = pc.z, c2 = pc.w;

        float sa, ca;
        __sincosf(pc.x * b1h, &sa, &ca);
        const float ca2 = ca*ca, sa2 = sa*sa, casa = ca*sa;
        const float ar = ca2*er, ai = ca2*ei;                         // A
        const float w2r = er*c2 - ei*s2, w2i = er*s2 + ei*c2;
        const float br = sa2*w2r, bi = sa2*w2i;                       // B
        const float w1r = er*cp - ei*sp, w1i = er*sp + ei*cp;
        const float cr = -casa*w1i, ci = casa*w1r;                    // C = i*casa*w1
        const float q1 = casa*E1;
        const float zc = q1*cp, zs = q1*sp;
        const float q2 = (ca2 - sa2)*E1;

        // In-place sweep. Produces: final carry (cF*,cZ) == boundary-out,
        // and oM* == Fm-mix of old slot 0 (for the previous thread).
        float oMr, oMi;
        float cFr = 0.f, cFi = 0.f, cZ = 0.f;
        #pragma unroll
        for (int j = 0; j < 3; ++j) {
            const float ofr = Fpr[j], ofi = Fpi[j];
            const float omr = Fmr[j], omi = Fmi[j];
            const float oz  = Zz[j];
            const float mr = ar*omr + ai*omi + br*ofr - bi*ofi + cr*oz;
            const float mi = ar*omi - ai*omr - br*ofi - bi*ofr - ci*oz;
            if (j == 0) { oMr = mr; oMi = mi; }
            else        { Fmr[j-1] = mr; Fmi[j-1] = mi; }
            Fpr[j] = cFr; Fpi[j] = cFi; Zz[j] = cZ;   // j=0 placeholder; patched below
            cFr = ar*ofr - ai*ofi + br*omr + bi*omi + cr*oz;
            cFi = ar*ofi + ai*ofr - br*omi + bi*omr + ci*oz;
            cZ  = q2*oz + zc*(ofi - omi) - zs*(ofr + omr);
            if (j == 0 && t0) cZ += rec;              // recovery -> lands in slot 1
        }

        // Boundary exchange (5 floats)
        float icFr = __shfl_up_sync(0xffffffffu, cFr, 1);
        float icFi = __shfl_up_sync(0xffffffffu, cFi, 1);
        float icZ  = __shfl_up_sync(0xffffffffu, cZ,  1);
        float iMr  = __shfl_down_sync(0xffffffffu, oMr, 1);
        float iMi  = __shfl_down_sync(0xffffffffu, oMi, 1);
        if (t0 | t7) { icFr = 0.f; icFi = 0.f; icZ = 0.f; }  // state-0 zero / zero sink
        if (t7) { iMr = 0.f; iMi = 0.f; }

        // Patch: slot 0 gets carry-in; slot 2 Fm gets next thread's slot-0 mix
        Fpr[0] = icFr; Fpi[0] = icFi; Zz[0] = icZ;
        Fmr[2] = iMr;  Fmi[2] = iMi;   // t==6: from t7's zero state -> Fm[20]=0

        // Stage 15 floats (t<=6); addresses distinct mod 32 -> conflict-free
        const int buf = p & 1;
        if (!t7) {
            float* row = buf ? row1 : row0;
            #pragma unroll
            for (int j = 0; j < 3; ++j) {
                row[j*5+0] = Fpr[j]; row[j*5+1] = Fpi[j];
                row[j*5+2] = Fmr[j]; row[j*5+3] = Fmi[j];
                row[j*5+4] = Zz[j];
            }
        }
        __syncwarp();
        // Coalesced copy-out: 105 float4 per warp (3 rounds + 9-lane tail)
        {
            const float4* s4 = buf ? s41 : s40;
            float4* o4 = out4 + (size_t)p * pst4;
            #pragma unroll
            for (int r = 0; r < 3; ++r) o4[lane + r*32] = s4[lane + r*32];
            if (lane < WST4 - 3*32) o4[lane + 3*32] = s4[lane + 3*32];
        }
        // no second barrier: buffer buf is next written at pulse p+2, which is
        // after syncwarp(p+1); each lane's copy(p) precedes its syncwarp(p+1).
    }
}

extern "C" void kernel_launch(void* const* d_in, const int* in_sizes, int n_in,
                              void* d_out, int out_size)
{
    const float* fa = (const float*)d_in[0];
    const float* ph = (const float*)d_in[1];
    const float* T1 = (const float*)d_in[2];
    const float* T2 = (const float*)d_in[3];
    const float* B0 = (const float*)d_in[4];
    const float* B1 = (const float*)d_in[5];
    const int*   tr = (const int*)d_in[6];

    int n_pulses = in_sizes[0];
    int n_batch  = in_sizes[2];
    if (n_pulses > NP) n_pulses = NP;

    int batches_per_block = WARPS * BPW;                                // 16
    int blocks = (n_batch + batches_per_block - 1) / batches_per_block; // 1024
    epg_kernel<<<blocks, THREADS>>>(fa, ph, T1, T2, B0, B1, tr,
                                    (float*)d_out, n_pulses, n_batch);
}

// round 14
// speedup vs baseline: 1.2168x; 1.2168x over previous
#include <cuda_runtime.h>
#include <cstdint>

// EPG simulation, 8 threads per batch (threads 0-6 hold 3 states, thread 7 is
// a zero sink). R12 overlap structure (boundary-first, shuffles early).
// R14: coefficients precomputed in 16-pulse chunks into shared (removes the
// x8-duplicated per-pulse coefficient build from the hot loop).

constexpr int NS   = 21;
constexpr int ROW  = NS * 5;            // 105 floats per (pulse,batch)
constexpr int NP   = 64;
constexpr int WARPS = 4;                // warps per block
constexpr int THREADS = WARPS * 32;     // 128 threads -> 16 batches per block
constexpr int BPB  = 16;                // batches per block
constexpr int BPW  = 4;                 // batches per warp
constexpr int WST  = BPW * ROW;         // 420 floats per warp stage
constexpr int WST4 = WST / 4;           // 105 float4
constexpr int CHUNK = 16;               // pulses per coefficient chunk
constexpr int CROW  = CHUNK * 12 + 4;   // 196 floats per batch (pad: bank-spread)

__global__ __launch_bounds__(THREADS)
void epg_kernel(const float* __restrict__ fa,
                const float* __restrict__ ph,
                const float* __restrict__ T1,
                const float* __restrict__ T2,
                const float* __restrict__ B0,
                const float* __restrict__ B1,
                const int*   __restrict__ trp,
                float* __restrict__ out,
                int n_pulses, int n_batch)
{
    __shared__ __align__(16) float4 pc4[NP];               // {fa, cos p, sin p, cos 2p}
    __shared__ float                ps2[NP];               // sin 2p
    __shared__ __align__(16) float  sbv[BPB][4];           // er, ei, E1, b1h
    __shared__ __align__(16) float  coef[BPB][CROW];       // 12544 B per chunk
    __shared__ __align__(16) float  stage[WARPS][2][WST];  // 13440 B

    const int tid  = threadIdx.x;
    const int warp = tid >> 5;
    const int lane = tid & 31;
    const int bw   = lane >> 3;          // batch within warp (0..3)
    const int t    = lane & 7;           // fragment within batch (0..7)
    const int bwl  = warp * BPW + bw;    // batch within block (0..15)

    const int tri = *trp;
    const float TR = (tri > 0 && tri < 1000000) ? (float)tri : __int_as_float(tri);

    // Pulse constants
    for (int p = tid; p < n_pulses; p += THREADS) {
        float s, c;
        sincosf(ph[p], &s, &c);
        pc4[p] = make_float4(fa[p], c, s, c * c - s * s);
        ps2[p] = 2.f * c * s;
    }
    // Per-batch constants
    if (tid < BPB) {
        int b2 = blockIdx.x * BPB + tid;
        if (b2 >= n_batch) b2 = n_batch - 1;
        const float E1 = __expf(-TR / T1[b2]);
        const float E2 = __expf(-TR / T2[b2]);
        float b0r, b0i;
        sincosf(6.283185307179586e-3f * B0[b2] * TR, &b0i, &b0r);
        sbv[tid][0] = E2 * b0r;
        sbv[tid][1] = E2 * b0i;
        sbv[tid][2] = E1;
        sbv[tid][3] = B1[b2] * 0.5f;
    }
    __syncthreads();

    const float rec = (t == 0) ? (1.f - sbv[bwl][2]) : 0.f;

    // 3 local slots; global state k = 3*t + j for t<=6; t==7 stays zero.
    float Fpr[3], Fpi[3], Fmr[3], Fmi[3], Zz[3];
    #pragma unroll
    for (int j = 0; j < 3; ++j) { Fpr[j]=0.f; Fpi[j]=0.f; Fmr[j]=0.f; Fmi[j]=0.f; Zz[j]=0.f; }
    const bool t0 = (t == 0), t7 = (t == 7);
    if (t0) Zz[0] = 1.f;

    const size_t pst4 = (size_t)n_batch * ROW / 4;
    float4* out4 = (float4*)out + ((size_t)blockIdx.x * BPB + warp * BPW) * ROW / 4;

    float* const row0 = &stage[warp][0][bw * ROW + t * 15];
    float* const row1 = &stage[warp][1][bw * ROW + t * 15];
    const float4* const s40 = (const float4*)stage[warp][0];
    const float4* const s41 = (const float4*)stage[warp][1];
    const float* const mycf = &coef[bwl][0];

    const int chunks = (n_pulses + CHUNK - 1) / CHUNK;
    for (int c = 0; c < chunks; ++c) {
        __syncthreads();    // previous chunk's coef reads complete

        // ---- precompute 256 coefficient sets (2 per thread) ----
        #pragma unroll
        for (int k2 = 0; k2 < 2; ++k2) {
            const int s  = tid + k2 * THREADS;
            const int bl = s >> 4;
            const int pp = s & 15;
            const int p  = c * CHUNK + pp;
            if (p < n_pulses) {
                const float4 pc = pc4[p];
                const float  s2 = ps2[p];
                const float  cp = pc.y, sp = pc.z, c2 = pc.w;
                const float er = sbv[bl][0], ei = sbv[bl][1];
                const float E1 = sbv[bl][2], b1h = sbv[bl][3];
                float sa, ca;
                __sincosf(pc.x * b1h, &sa, &ca);
                const float ca2 = ca*ca, sa2 = sa*sa, casa = ca*sa;
                const float w2r = er*c2 - ei*s2, w2i = er*s2 + ei*c2;
                const float w1r = er*cp - ei*sp, w1i = er*sp + ei*cp;
                const float q1  = casa*E1;
                float4* dst = (float4*)&coef[bl][pp * 12];
                dst[0] = make_float4(ca2*er, ca2*ei, sa2*w2r, sa2*w2i);   // A, B
                dst[1] = make_float4(-casa*w1i, casa*w1r, q1*cp, q1*sp);  // C, zc, zs
                dst[2] = make_float4((ca2 - sa2)*E1, 0.f, 0.f, 0.f);      // q2
            }
        }
        __syncthreads();

        // ---- 16 pulses with precomputed coefficients ----
        const int pend = (n_pulses - c * CHUNK < CHUNK) ? (n_pulses - c * CHUNK) : CHUNK;
        for (int pp = 0; pp < pend; ++pp) {
            const int p = c * CHUNK + pp;
            const float4 c0 = *(const float4*)(mycf + pp * 12);      // broadcast per batch
            const float4 c1 = *(const float4*)(mycf + pp * 12 + 4);
            const float  q2 = mycf[pp * 12 + 8];
            const float ar = c0.x, ai = c0.y, br = c0.z, bi = c0.w;
            const float cr = c1.x, ci = c1.y, zc = c1.z, zs = c1.w;

            // Boundary values from OLD state (issued early -> shuffles overlap sweep)
            const float ocFr = ar*Fpr[2] - ai*Fpi[2] + br*Fmr[2] + bi*Fmi[2] + cr*Zz[2];
            const float ocFi = ar*Fpi[2] + ai*Fpr[2] - br*Fmi[2] + bi*Fmr[2] + ci*Zz[2];
            const float ocZ  = q2*Zz[2] + zc*(Fpi[2]-Fmi[2]) - zs*(Fpr[2]+Fmr[2]);
            const float oMr  = ar*Fmr[0] + ai*Fmi[0] + br*Fpr[0] - bi*Fpi[0] + cr*Zz[0];
            const float oMi  = ar*Fmi[0] - ai*Fmr[0] - br*Fpi[0] - bi*Fpr[0] - ci*Zz[0];

            float icFr = __shfl_up_sync(0xffffffffu, ocFr, 1);
            float icFi = __shfl_up_sync(0xffffffffu, ocFi, 1);
            float icZ  = __shfl_up_sync(0xffffffffu, ocZ,  1);
            float iMr  = __shfl_down_sync(0xffffffffu, oMr, 1);
            float iMi  = __shfl_down_sync(0xffffffffu, oMi, 1);
            if (t0 | t7) { icFr = 0.f; icFi = 0.f; icZ = 0.f; }
            if (t7) { iMr = 0.f; iMi = 0.f; }

            // Local in-place sweep; carries realize the shift
            float cFr = icFr, cFi = icFi, cZ = icZ;
            #pragma unroll
            for (int j = 0; j < 3; ++j) {
                const float ofr = Fpr[j], ofi = Fpi[j];
                const float omr = Fmr[j], omi = Fmi[j];
                const float oz  = Zz[j];
                if (j > 0) {
                    Fmr[j-1] = ar*omr + ai*omi + br*ofr - bi*ofi + cr*oz;
                    Fmi[j-1] = ar*omi - ai*omr - br*ofi - bi*ofr - ci*oz;
                }
                Fpr[j] = cFr; Fpi[j] = cFi; Zz[j] = cZ;
                cFr = ar*ofr - ai*ofi + br*omr + bi*omi + cr*oz;
                cFi = ar*ofi + ai*ofr - br*omi + bi*omr + ci*oz;
                cZ  = q2*oz + zc*(ofi - omi) - zs*(ofr + omr);
                if (j == 0 && t0) cZ += rec;   // recovery -> lands in slot 1
            }
            Fmr[2] = iMr; Fmi[2] = iMi;        // t==6: from t7's zero -> Fm[20]=0

            // Stage 15 floats (t<=6); conflict-free scalar STS
            const int buf = p & 1;
            if (!t7) {
                float* row = buf ? row1 : row0;
                #pragma unroll
                for (int j = 0; j < 3; ++j) {
                    row[j*5+0] = Fpr[j]; row[j*5+1] = Fpi[j];
                    row[j*5+2] = Fmr[j]; row[j*5+3] = Fmi[j];
                    row[j*5+4] = Zz[j];
                }
            }
            __syncwarp();
            // Coalesced copy-out: 105 float4 per warp
            {
                const float4* s4 = buf ? s41 : s40;
                float4* o4 = out4 + (size_t)p * pst4;
                #pragma unroll
                for (int r = 0; r < 3; ++r) o4[lane + r*32] = s4[lane + r*32];
                if (lane < WST4 - 3*32) o4[lane + 3*32] = s4[lane + 3*32];
            }
            // buffer buf next written at pulse p+2 (after syncwarp(p+1)).
        }
    }
}

extern "C" void kernel_launch(void* const* d_in, const int* in_sizes, int n_in,
                              void* d_out, int out_size)
{
    const float* fa = (const float*)d_in[0];
    const float* ph = (const float*)d_in[1];
    const float* T1 = (const float*)d_in[2];
    const float* T2 = (const float*)d_in[3];
    const float* B0 = (const float*)d_in[4];
    const float* B1 = (const float*)d_in[5];
    const int*   tr = (const int*)d_in[6];

    int n_pulses = in_sizes[0];
    int n_batch  = in_sizes[2];
    if (n_pulses > NP) n_pulses = NP;

    int blocks = (n_batch + BPB - 1) / BPB;   // 1024
    epg_kernel<<<blocks, THREADS>>>(fa, ph, T1, T2, B0, B1, tr,
                                    (float*)d_out, n_pulses, n_batch);
}